// round 13
// baseline (speedup 1.0000x reference)
#include <cuda_runtime.h>
#include <cuda_bf16.h>
#include <cstdint>
#include <stdint.h>
#include <math.h>

#define N_PATCH 3136
#define N_PAD   3200
#define N_LIB   16384
#define DIM     768
#define FH      56
#define IMG     224

#define BM 128
#define BN 128
#define BK 32
#define PAD 40            // smem k-stride in bf16 (80B) -> conflict-free ldmatrix
#define NSTAGES 3
#define NSTEPS (DIM / BK) // 24

// dynamic smem layout (bytes)
#define STAGE_ELEMS (BM * PAD)                    // 5120 bf16
#define STAGE_BYTES (STAGE_ELEMS * 2)             // 10240
#define SM_B_OFF    (NSTAGES * STAGE_BYTES)       // 30720
#define SM_KEY_OFF  (2 * NSTAGES * STAGE_BYTES)   // 61440
#define SM_A2_OFF   (SM_KEY_OFF + BM * 8)         // 62464
#define SM_B2_OFF   (SM_A2_OFF + BM * 4)          // 62976
#define SMEM_TOTAL  (SM_B2_OFF + BN * 4)          // 63488  (x2 CTAs = 127KB < 227KB)

// ---------------- scratch (device globals; no allocation allowed) ----------
__device__ __nv_bfloat16 g_Pb[N_PAD * DIM];
__device__ __nv_bfloat16 g_Lb[N_LIB * DIM];
__device__ float g_a2[N_PATCH];
__device__ float g_b2[N_LIB];
__device__ unsigned long long g_minkey[N_PATCH];
__device__ float g_minval[N_PATCH];
__device__ unsigned long long g_amax_key;   // (bits(min_val)<<32) | (~idx)
__device__ float g_wdist2[N_LIB];

// ---------------- helpers -----------------------------------------------------
__device__ __forceinline__ uint32_t s2u(const void* p) {
    return (uint32_t)__cvta_generic_to_shared(p);
}
__device__ __forceinline__ void cp16(uint32_t dst, const void* src) {
    asm volatile("cp.async.cg.shared.global [%0], [%1], 16;\n" :: "r"(dst), "l"(src));
}

// ---------------- unified prep: normalize/convert + row sumsq (+ inits) -------
// warp w in [0, N_PAD)           -> patch row w   (normalize, bf16, a2, minkey)
// warp w in [N_PAD, N_PAD+N_LIB) -> lib row w-N_PAD (bf16, b2)
__global__ void k_prep(const float* __restrict__ patch,
                       const float* __restrict__ lib,
                       const float* __restrict__ mean,
                       const float* __restrict__ stdv) {
    if (blockIdx.x == 0 && threadIdx.x == 0) g_amax_key = 0ULL;
    int w = (blockIdx.x * blockDim.x + threadIdx.x) >> 5;
    int lane = threadIdx.x & 31;
    if (w >= N_PAD + N_LIB) return;

    if (w < N_PAD) {
        if (w >= N_PATCH) {   // zero pad rows
            float4 z4 = make_float4(0.f, 0.f, 0.f, 0.f);
            for (int d = lane * 8; d < DIM; d += 256)
                *(float4*)(g_Pb + (size_t)w * DIM + d) = z4;   // 8 bf16 = 16B
            return;
        }
        float mu = mean[0], inv = 1.f / stdv[0];
        float s = 0.f;
        #pragma unroll
        for (int it = 0; it < 3; ++it) {
            int d = lane * 8 + it * 256;
            float4 v0 = *(const float4*)(patch + (size_t)w * DIM + d);
            float4 v1 = *(const float4*)(patch + (size_t)w * DIM + d + 4);
            v0.x = (v0.x - mu) * inv; v0.y = (v0.y - mu) * inv;
            v0.z = (v0.z - mu) * inv; v0.w = (v0.w - mu) * inv;
            v1.x = (v1.x - mu) * inv; v1.y = (v1.y - mu) * inv;
            v1.z = (v1.z - mu) * inv; v1.w = (v1.w - mu) * inv;
            __nv_bfloat162 b0 = __floats2bfloat162_rn(v0.x, v0.y);
            __nv_bfloat162 b1 = __floats2bfloat162_rn(v0.z, v0.w);
            __nv_bfloat162 b2 = __floats2bfloat162_rn(v1.x, v1.y);
            __nv_bfloat162 b3 = __floats2bfloat162_rn(v1.z, v1.w);
            *(__nv_bfloat162*)(g_Pb + (size_t)w * DIM + d)     = b0;
            *(__nv_bfloat162*)(g_Pb + (size_t)w * DIM + d + 2) = b1;
            *(__nv_bfloat162*)(g_Pb + (size_t)w * DIM + d + 4) = b2;
            *(__nv_bfloat162*)(g_Pb + (size_t)w * DIM + d + 6) = b3;
            s += v0.x * v0.x + v0.y * v0.y + v0.z * v0.z + v0.w * v0.w;
            s += v1.x * v1.x + v1.y * v1.y + v1.z * v1.z + v1.w * v1.w;
        }
        #pragma unroll
        for (int off = 16; off; off >>= 1) s += __shfl_down_sync(0xffffffffu, s, off);
        if (lane == 0) {
            g_a2[w] = s;
            g_minkey[w] = ~0ULL;
        }
    } else {
        int r = w - N_PAD;
        float s = 0.f;
        #pragma unroll
        for (int it = 0; it < 3; ++it) {
            int d = lane * 8 + it * 256;
            float4 v0 = *(const float4*)(lib + (size_t)r * DIM + d);
            float4 v1 = *(const float4*)(lib + (size_t)r * DIM + d + 4);
            __nv_bfloat162 b0 = __floats2bfloat162_rn(v0.x, v0.y);
            __nv_bfloat162 b1 = __floats2bfloat162_rn(v0.z, v0.w);
            __nv_bfloat162 b2 = __floats2bfloat162_rn(v1.x, v1.y);
            __nv_bfloat162 b3 = __floats2bfloat162_rn(v1.z, v1.w);
            *(__nv_bfloat162*)(g_Lb + (size_t)r * DIM + d)     = b0;
            *(__nv_bfloat162*)(g_Lb + (size_t)r * DIM + d + 2) = b1;
            *(__nv_bfloat162*)(g_Lb + (size_t)r * DIM + d + 4) = b2;
            *(__nv_bfloat162*)(g_Lb + (size_t)r * DIM + d + 6) = b3;
            s += v0.x * v0.x + v0.y * v0.y + v0.z * v0.z + v0.w * v0.w;
            s += v1.x * v1.x + v1.y * v1.y + v1.z * v1.z + v1.w * v1.w;
        }
        #pragma unroll
        for (int off = 16; off; off >>= 1) s += __shfl_down_sync(0xffffffffu, s, off);
        if (lane == 0) g_b2[r] = s;
    }
}

// ---------------- tensor-core GEMM + fused row-min (R8 config) ----------------
__global__ __launch_bounds__(256, 2)
void k_gemm_min_tc() {
    extern __shared__ char smem[];
    __nv_bfloat16* AsBase = (__nv_bfloat16*)smem;
    __nv_bfloat16* BsBase = (__nv_bfloat16*)(smem + SM_B_OFF);
    unsigned long long* skey = (unsigned long long*)(smem + SM_KEY_OFF);
    float* sa2 = (float*)(smem + SM_A2_OFF);
    float* sb2 = (float*)(smem + SM_B2_OFF);

    const int tid  = threadIdx.x;
    const int warp = tid >> 5, lane = tid & 31;
    const int wm = warp >> 2, wn = warp & 3;   // 2 x 4 warp grid
    const int bx = blockIdx.x, by = blockIdx.y;

    for (int i = tid; i < BM; i += 256) {
        skey[i] = ~0ULL;
        int gi = by * BM + i;
        sa2[i] = (gi < N_PATCH) ? g_a2[gi] : 0.f;
        sb2[i] = g_b2[bx * BN + i];
    }

    const __nv_bfloat16* Ag = g_Pb + (size_t)(by * BM) * DIM;
    const __nv_bfloat16* Bg = g_Lb + (size_t)(bx * BN) * DIM;

    float acc[4][4][4];
    #pragma unroll
    for (int a = 0; a < 4; ++a)
        #pragma unroll
        for (int b = 0; b < 4; ++b)
            #pragma unroll
            for (int c = 0; c < 4; ++c) acc[a][b][c] = 0.f;

    // stage loader: 128 rows x 32 cols bf16 for A and B each
    auto load_stage = [&](int st) {
        int buf = st % NSTAGES;
        __nv_bfloat16* A = AsBase + buf * STAGE_ELEMS;
        __nv_bfloat16* B = BsBase + buf * STAGE_ELEMS;
        int k0 = st * BK;
        #pragma unroll
        for (int l = 0; l < 2; ++l) {
            int chunk = tid + l * 256;           // 0..511
            int row = chunk >> 2;
            int kc  = (chunk & 3) * 8;           // 8 bf16 = 16B
            cp16(s2u(A + row * PAD + kc), Ag + (size_t)row * DIM + k0 + kc);
            cp16(s2u(B + row * PAD + kc), Bg + (size_t)row * DIM + k0 + kc);
        }
        asm volatile("cp.async.commit_group;\n" ::);
    };

    load_stage(0);
    load_stage(1);

    for (int it = 0; it < NSTEPS; ++it) {
        if (it + 2 < NSTEPS) { asm volatile("cp.async.wait_group 1;\n" ::); }
        else                 { asm volatile("cp.async.wait_group 0;\n" ::); }
        __syncthreads();
        if (it + 2 < NSTEPS) load_stage(it + 2);

        int buf = it % NSTAGES;
        const __nv_bfloat16* as = AsBase + buf * STAGE_ELEMS;
        const __nv_bfloat16* bs = BsBase + buf * STAGE_ELEMS;

        #pragma unroll
        for (int ks = 0; ks < 2; ++ks) {
            uint32_t af[4][4], bf[4][2];
            #pragma unroll
            for (int im = 0; im < 4; ++im) {
                int r = wm * 64 + im * 16 + (lane & 15);
                int c = ks * 16 + (lane >> 4) * 8;
                uint32_t addr = s2u(&as[r * PAD + c]);
                asm volatile(
                    "ldmatrix.sync.aligned.m8n8.x4.shared.b16 {%0,%1,%2,%3}, [%4];\n"
                    : "=r"(af[im][0]), "=r"(af[im][1]), "=r"(af[im][2]), "=r"(af[im][3])
                    : "r"(addr));
            }
            #pragma unroll
            for (int in2 = 0; in2 < 2; ++in2) {
                int r = wn * 32 + in2 * 16 + (lane & 7) + ((lane >> 4) << 3);
                int c = ks * 16 + ((lane >> 3) & 1) * 8;
                uint32_t addr = s2u(&bs[r * PAD + c]);
                asm volatile(
                    "ldmatrix.sync.aligned.m8n8.x4.shared.b16 {%0,%1,%2,%3}, [%4];\n"
                    : "=r"(bf[in2 * 2][0]), "=r"(bf[in2 * 2][1]),
                      "=r"(bf[in2 * 2 + 1][0]), "=r"(bf[in2 * 2 + 1][1])
                    : "r"(addr));
            }
            #pragma unroll
            for (int im = 0; im < 4; ++im)
                #pragma unroll
                for (int in = 0; in < 4; ++in) {
                    asm volatile(
                        "mma.sync.aligned.m16n8k16.row.col.f32.bf16.bf16.f32 "
                        "{%0,%1,%2,%3}, {%4,%5,%6,%7}, {%8,%9}, {%0,%1,%2,%3};\n"
                        : "+f"(acc[im][in][0]), "+f"(acc[im][in][1]),
                          "+f"(acc[im][in][2]), "+f"(acc[im][in][3])
                        : "r"(af[im][0]), "r"(af[im][1]), "r"(af[im][2]), "r"(af[im][3]),
                          "r"(bf[in][0]), "r"(bf[in][1]));
                }
        }
    }

    // epilogue: d2 = a2 + b2 - 2*dot -> packed min key per row
    const int tig = lane & 3, grp = lane >> 2;
    #pragma unroll
    for (int im = 0; im < 4; ++im) {
        int r0 = wm * 64 + im * 16 + grp;
        int r1 = r0 + 8;
        float a20 = sa2[r0], a21 = sa2[r1];
        unsigned long long k0 = ~0ULL, k1 = ~0ULL;
        #pragma unroll
        for (int in = 0; in < 4; ++in) {
            int cl = wn * 32 + in * 8 + 2 * tig;
            unsigned j0 = (unsigned)(bx * BN + cl);
            float b20 = sb2[cl], b21 = sb2[cl + 1];

            float d;
            unsigned long long kk;
            d = fmaxf(a20 + b20 - 2.f * acc[im][in][0], 0.f);
            kk = ((unsigned long long)__float_as_uint(d) << 32) | j0;
            k0 = kk < k0 ? kk : k0;
            d = fmaxf(a20 + b21 - 2.f * acc[im][in][1], 0.f);
            kk = ((unsigned long long)__float_as_uint(d) << 32) | (j0 + 1);
            k0 = kk < k0 ? kk : k0;
            d = fmaxf(a21 + b20 - 2.f * acc[im][in][2], 0.f);
            kk = ((unsigned long long)__float_as_uint(d) << 32) | j0;
            k1 = kk < k1 ? kk : k1;
            d = fmaxf(a21 + b21 - 2.f * acc[im][in][3], 0.f);
            kk = ((unsigned long long)__float_as_uint(d) << 32) | (j0 + 1);
            k1 = kk < k1 ? kk : k1;
        }
        atomicMin(&skey[r0], k0);
        atomicMin(&skey[r1], k1);
    }
    __syncthreads();

    if (tid < BM) {
        int gi = by * BM + tid;
        if (gi < N_PATCH) atomicMin(&g_minkey[gi], skey[tid]);
    }
}

// ---------------- min_val + packed argmax (parallel) ---------------------------
__global__ void k_minval() {
    __shared__ unsigned long long sk[256];
    int t = threadIdx.x;
    int i = blockIdx.x * blockDim.x + t;
    unsigned long long key = 0ULL;
    if (i < N_PATCH) {
        unsigned long long k = g_minkey[i];
        float v = sqrtf(__uint_as_float((unsigned)(k >> 32)));
        g_minval[i] = v;
        key = ((unsigned long long)__float_as_uint(v) << 32)
            | (unsigned)(0xFFFFFFFFu - (unsigned)i);   // max value, then min index
    }
    sk[t] = key; __syncthreads();
    for (int s = 128; s; s >>= 1) {
        if (t < s) { if (sk[t + s] > sk[t]) sk[t] = sk[t + s]; }
        __syncthreads();
    }
    if (t == 0) atomicMax(&g_amax_key, sk[0]);
}

// ---------------- distances of m_star to whole bank --------------------------
__global__ void k_wdist(const float* __restrict__ lib) {
    int w = (blockIdx.x * blockDim.x + threadIdx.x) >> 5;
    int lane = threadIdx.x & 31;
    if (w >= N_LIB) return;
    int sidx = (int)(0xFFFFFFFFu - (unsigned)(g_amax_key & 0xFFFFFFFFu));
    int mstar = (int)(g_minkey[sidx] & 0xFFFFFFFFu);
    const float* ms = lib + (size_t)mstar * DIM;
    const float* rj = lib + (size_t)w * DIM;
    float s = 0.f;
    for (int d = lane * 4; d < DIM; d += 128) {
        float4 a = *(const float4*)(rj + d);
        float4 b = *(const float4*)(ms + d);
        float dx = a.x - b.x, dy = a.y - b.y, dz = a.z - b.z, dw = a.w - b.w;
        s += dx * dx + dy * dy + dz * dz + dw * dw;
    }
    #pragma unroll
    for (int off = 16; off; off >>= 1) s += __shfl_down_sync(0xffffffffu, s, off);
    if (lane == 0) g_wdist2[w] = s;
}

// ---------------- fused: 3 smallest + final scalar score ----------------------
__device__ __forceinline__ void ins3(unsigned long long k, unsigned long long* b) {
    if (k < b[2]) {
        if (k < b[1]) {
            b[2] = b[1];
            if (k < b[0]) { b[1] = b[0]; b[0] = k; } else b[1] = k;
        } else b[2] = k;
    }
}

__global__ void k_top3_score(const float* __restrict__ patch,
                             const float* __restrict__ mean,
                             const float* __restrict__ stdv,
                             const float* __restrict__ lib,
                             float* __restrict__ out) {
    __shared__ unsigned long long sk[1024][3];
    __shared__ float sa[1024], sb[1024];
    int t = threadIdx.x;

    // phase 1: top-3 smallest of wdist (stable by index)
    unsigned long long b3[3] = {~0ULL, ~0ULL, ~0ULL};
    for (int j = t; j < N_LIB; j += 1024) {
        unsigned long long key =
            ((unsigned long long)__float_as_uint(g_wdist2[j]) << 32) | (unsigned)j;
        ins3(key, b3);
    }
    sk[t][0] = b3[0]; sk[t][1] = b3[1]; sk[t][2] = b3[2];
    __syncthreads();
    for (int s = 512; s; s >>= 1) {
        if (t < s) {
            ins3(sk[t + s][0], &sk[t][0]);
            ins3(sk[t + s][1], &sk[t][0]);
            ins3(sk[t + s][2], &sk[t][0]);
        }
        __syncthreads();
    }
    int nn1 = (int)(sk[0][1] & 0xFFFFFFFFu);
    int nn2 = (int)(sk[0][2] & 0xFFFFFFFFu);

    // phase 2: score using nn1, nn2 (all threads have them post-sync)
    unsigned long long ak = g_amax_key;
    int sidx = (int)(0xFFFFFFFFu - (unsigned)(ak & 0xFFFFFFFFu));
    float sstar = __uint_as_float((unsigned)(ak >> 32));
    float mu = mean[0], inv = 1.f / stdv[0];
    const float* mt = patch + (size_t)sidx * DIM;
    const float* n1 = lib + (size_t)nn1 * DIM;
    const float* n2 = lib + (size_t)nn2 * DIM;
    float a = 0.f, b = 0.f;
    if (t < DIM) {
        float m = (mt[t] - mu) * inv;
        float x = m - n1[t]; a = x * x;
        float y = m - n2[t]; b = y * y;
    }
    sa[t] = a; sb[t] = b; __syncthreads();
    for (int s = 512; s; s >>= 1) {
        if (t < s) { sa[t] += sa[t + s]; sb[t] += sb[t + s]; }
        __syncthreads();
    }
    if (t == 0) {
        float sq = sqrtf((float)DIM);
        float k0 = sqrtf(fmaxf(sa[0], 0.f));
        float k1 = sqrtf(fmaxf(sb[0], 0.f));
        float w = 1.0f - expf(sstar / sq) / (expf(k0 / sq) + expf(k1 / sq));
        out[0] = w * sstar;
    }
}

// ---------------- fully fused resize(56->224) + 9-tap separable blur ----------
__device__ __forceinline__ int refl(int i, int n) {
    if (i < 0) i = -i;
    if (i >= n) i = 2 * n - 2 - i;
    return i;
}
__device__ __forceinline__ void gweights(float* w) {
    float s = 0.f;
    #pragma unroll
    for (int t = 0; t < 9; ++t) { float d = (float)(t - 4); w[t] = expf(-d * d / 32.0f); s += w[t]; }
    #pragma unroll
    for (int t = 0; t < 9; ++t) w[t] /= s;
}
__device__ __forceinline__ float resized_val(int y, int x) {
    float fy = (y + 0.5f) * 0.25f - 0.5f;
    float fx = (x + 0.5f) * 0.25f - 0.5f;
    int y0 = (int)floorf(fy); float wy = fy - (float)y0;
    int x0 = (int)floorf(fx); float wx = fx - (float)x0;
    int y0c = min(max(y0, 0), FH - 1), y1c = min(max(y0 + 1, 0), FH - 1);
    int x0c = min(max(x0, 0), FH - 1), x1c = min(max(x0 + 1, 0), FH - 1);
    float v00 = g_minval[y0c * FH + x0c];
    float v01 = g_minval[y0c * FH + x1c];
    float v10 = g_minval[y1c * FH + x0c];
    float v11 = g_minval[y1c * FH + x1c];
    return v00 * (1.f - wy) * (1.f - wx) + v01 * (1.f - wy) * wx
         + v10 * wy * (1.f - wx) + v11 * wy * wx;
}

#define BR 8   // output rows per block; halo = BR + 8 = 16 h-blurred rows
__global__ void k_blur(float* __restrict__ out) {
    __shared__ float h[BR + 8][IMG];
    int r0 = blockIdx.x * BR;
    int t = threadIdx.x;           // 256 threads
    float w[9]; gweights(w);

    // h[ry] = horizontal blur of global row refl(r0 - 4 + ry)
    for (int idx = t; idx < (BR + 8) * IMG; idx += 256) {
        int ry = idx / IMG, x = idx % IMG;
        int y = refl(r0 - 4 + ry, IMG);
        float acc = 0.f;
        #pragma unroll
        for (int k = 0; k < 9; ++k) acc += w[k] * resized_val(y, refl(x + k - 4, IMG));
        h[ry][x] = acc;
    }
    __syncthreads();

    // output row g = r0 + ry needs h-blur of rows refl(g + k - 4) == h[ry + k]
    for (int idx = t; idx < BR * IMG; idx += 256) {
        int ry = idx / IMG, x = idx % IMG;
        float acc = 0.f;
        #pragma unroll
        for (int k = 0; k < 9; ++k) acc += w[k] * h[ry + k][x];
        out[(r0 + ry) * IMG + x] = acc;
    }
}

// ---------------- launch ------------------------------------------------------
extern "C" void kernel_launch(void* const* d_in, const int* in_sizes, int n_in,
                              void* d_out, int out_size) {
    const float* patch = (const float*)d_in[0];
    const float* lib   = (const float*)d_in[1];
    const float* mean  = (const float*)d_in[2];
    const float* stdv  = (const float*)d_in[3];
    float* out = (float*)d_out;

    cudaFuncSetAttribute(k_gemm_min_tc,
                         cudaFuncAttributeMaxDynamicSharedMemorySize, SMEM_TOTAL);

    k_prep<<<((N_PAD + N_LIB) * 32 + 255) / 256, 256>>>(patch, lib, mean, stdv);

    dim3 grid(N_LIB / BN, N_PAD / BM);
    k_gemm_min_tc<<<grid, 256, SMEM_TOTAL>>>();

    k_minval<<<(N_PATCH + 255) / 256, 256>>>();
    k_wdist<<<(N_LIB * 32 + 255) / 256, 256>>>(lib);
    k_top3_score<<<1, 1024>>>(patch, mean, stdv, lib, out);

    k_blur<<<IMG / BR, 256>>>(out + 1);
}

// round 14
// speedup vs baseline: 1.0388x; 1.0388x over previous
#include <cuda_runtime.h>
#include <cuda_bf16.h>
#include <cstdint>
#include <stdint.h>
#include <math.h>

#define N_PATCH 3136
#define N_PAD   3200
#define N_LIB   16384
#define DIM     768
#define FH      56
#define IMG     224

#define BM 128
#define BN 128
#define BK 32
#define PAD 40            // smem k-stride in bf16 (80B) -> conflict-free ldmatrix
#define NSTAGES 3
#define NSTEPS (DIM / BK) // 24

// dynamic smem layout (bytes)
#define STAGE_ELEMS (BM * PAD)                    // 5120 bf16
#define STAGE_BYTES (STAGE_ELEMS * 2)             // 10240
#define SM_B_OFF    (NSTAGES * STAGE_BYTES)       // 30720
#define SM_KEY_OFF  (2 * NSTAGES * STAGE_BYTES)   // 61440
#define SM_A2_OFF   (SM_KEY_OFF + BM * 8)         // 62464
#define SM_B2_OFF   (SM_A2_OFF + BM * 4)          // 62976
#define SMEM_TOTAL  (SM_B2_OFF + BN * 4)          // 63488  (x2 CTAs = 127KB < 227KB)

// ---------------- scratch (device globals; no allocation allowed) ----------
__device__ __nv_bfloat16 g_Pb[N_PAD * DIM];
__device__ __nv_bfloat16 g_Lb[N_LIB * DIM];
__device__ float g_a2[N_PATCH];
__device__ float g_b2[N_LIB];
__device__ unsigned long long g_minkey[N_PATCH];
__device__ float g_minval[N_PATCH];
__device__ unsigned long long g_amax_key;   // (bits(min_val)<<32) | (~idx)
__device__ float g_wdist2[N_LIB];
__device__ float g_tmp[IMG * IMG];

// ---------------- helpers -----------------------------------------------------
__device__ __forceinline__ uint32_t s2u(const void* p) {
    return (uint32_t)__cvta_generic_to_shared(p);
}
__device__ __forceinline__ void cp16(uint32_t dst, const void* src) {
    asm volatile("cp.async.cg.shared.global [%0], [%1], 16;\n" :: "r"(dst), "l"(src));
}

// ---------------- unified prep (R12 loop bodies, single launch) ---------------
// warp w in [0, N_PAD)           -> patch row w   (normalize, bf16, a2, minkey)
// warp w in [N_PAD, N_PAD+N_LIB) -> lib row w-N_PAD (bf16, b2)
__global__ void k_prep(const float* __restrict__ patch,
                       const float* __restrict__ lib,
                       const float* __restrict__ mean,
                       const float* __restrict__ stdv) {
    if (blockIdx.x == 0 && threadIdx.x == 0) g_amax_key = 0ULL;
    int w = (blockIdx.x * blockDim.x + threadIdx.x) >> 5;
    int lane = threadIdx.x & 31;
    if (w >= N_PAD + N_LIB) return;

    if (w < N_PAD) {
        if (w >= N_PATCH) {   // zero pad rows
            __nv_bfloat162 z = __floats2bfloat162_rn(0.f, 0.f);
            for (int d = lane * 4; d < DIM; d += 128) {
                *(__nv_bfloat162*)(g_Pb + (size_t)w * DIM + d)     = z;
                *(__nv_bfloat162*)(g_Pb + (size_t)w * DIM + d + 2) = z;
            }
            return;
        }
        float mu = mean[0], inv = 1.f / stdv[0];
        float s = 0.f;
        for (int d = lane * 4; d < DIM; d += 128) {
            float4 v = *(const float4*)(patch + (size_t)w * DIM + d);
            v.x = (v.x - mu) * inv; v.y = (v.y - mu) * inv;
            v.z = (v.z - mu) * inv; v.w = (v.w - mu) * inv;
            *(__nv_bfloat162*)(g_Pb + (size_t)w * DIM + d)     = __floats2bfloat162_rn(v.x, v.y);
            *(__nv_bfloat162*)(g_Pb + (size_t)w * DIM + d + 2) = __floats2bfloat162_rn(v.z, v.w);
            s += v.x * v.x + v.y * v.y + v.z * v.z + v.w * v.w;
        }
        #pragma unroll
        for (int off = 16; off; off >>= 1) s += __shfl_down_sync(0xffffffffu, s, off);
        if (lane == 0) {
            g_a2[w] = s;
            g_minkey[w] = ~0ULL;
        }
    } else {
        int r = w - N_PAD;
        float s = 0.f;
        for (int d = lane * 4; d < DIM; d += 128) {
            float4 v = *(const float4*)(lib + (size_t)r * DIM + d);
            *(__nv_bfloat162*)(g_Lb + (size_t)r * DIM + d)     = __floats2bfloat162_rn(v.x, v.y);
            *(__nv_bfloat162*)(g_Lb + (size_t)r * DIM + d + 2) = __floats2bfloat162_rn(v.z, v.w);
            s += v.x * v.x + v.y * v.y + v.z * v.z + v.w * v.w;
        }
        #pragma unroll
        for (int off = 16; off; off >>= 1) s += __shfl_down_sync(0xffffffffu, s, off);
        if (lane == 0) g_b2[r] = s;
    }
}

// ---------------- tensor-core GEMM + fused row-min (R8 config) ----------------
__global__ __launch_bounds__(256, 2)
void k_gemm_min_tc() {
    extern __shared__ char smem[];
    __nv_bfloat16* AsBase = (__nv_bfloat16*)smem;
    __nv_bfloat16* BsBase = (__nv_bfloat16*)(smem + SM_B_OFF);
    unsigned long long* skey = (unsigned long long*)(smem + SM_KEY_OFF);
    float* sa2 = (float*)(smem + SM_A2_OFF);
    float* sb2 = (float*)(smem + SM_B2_OFF);

    const int tid  = threadIdx.x;
    const int warp = tid >> 5, lane = tid & 31;
    const int wm = warp >> 2, wn = warp & 3;   // 2 x 4 warp grid
    const int bx = blockIdx.x, by = blockIdx.y;

    for (int i = tid; i < BM; i += 256) {
        skey[i] = ~0ULL;
        int gi = by * BM + i;
        sa2[i] = (gi < N_PATCH) ? g_a2[gi] : 0.f;
        sb2[i] = g_b2[bx * BN + i];
    }

    const __nv_bfloat16* Ag = g_Pb + (size_t)(by * BM) * DIM;
    const __nv_bfloat16* Bg = g_Lb + (size_t)(bx * BN) * DIM;

    float acc[4][4][4];
    #pragma unroll
    for (int a = 0; a < 4; ++a)
        #pragma unroll
        for (int b = 0; b < 4; ++b)
            #pragma unroll
            for (int c = 0; c < 4; ++c) acc[a][b][c] = 0.f;

    // stage loader: 128 rows x 32 cols bf16 for A and B each
    auto load_stage = [&](int st) {
        int buf = st % NSTAGES;
        __nv_bfloat16* A = AsBase + buf * STAGE_ELEMS;
        __nv_bfloat16* B = BsBase + buf * STAGE_ELEMS;
        int k0 = st * BK;
        #pragma unroll
        for (int l = 0; l < 2; ++l) {
            int chunk = tid + l * 256;           // 0..511
            int row = chunk >> 2;
            int kc  = (chunk & 3) * 8;           // 8 bf16 = 16B
            cp16(s2u(A + row * PAD + kc), Ag + (size_t)row * DIM + k0 + kc);
            cp16(s2u(B + row * PAD + kc), Bg + (size_t)row * DIM + k0 + kc);
        }
        asm volatile("cp.async.commit_group;\n" ::);
    };

    load_stage(0);
    load_stage(1);

    for (int it = 0; it < NSTEPS; ++it) {
        if (it + 2 < NSTEPS) { asm volatile("cp.async.wait_group 1;\n" ::); }
        else                 { asm volatile("cp.async.wait_group 0;\n" ::); }
        __syncthreads();
        if (it + 2 < NSTEPS) load_stage(it + 2);

        int buf = it % NSTAGES;
        const __nv_bfloat16* as = AsBase + buf * STAGE_ELEMS;
        const __nv_bfloat16* bs = BsBase + buf * STAGE_ELEMS;

        #pragma unroll
        for (int ks = 0; ks < 2; ++ks) {
            uint32_t af[4][4], bf[4][2];
            #pragma unroll
            for (int im = 0; im < 4; ++im) {
                int r = wm * 64 + im * 16 + (lane & 15);
                int c = ks * 16 + (lane >> 4) * 8;
                uint32_t addr = s2u(&as[r * PAD + c]);
                asm volatile(
                    "ldmatrix.sync.aligned.m8n8.x4.shared.b16 {%0,%1,%2,%3}, [%4];\n"
                    : "=r"(af[im][0]), "=r"(af[im][1]), "=r"(af[im][2]), "=r"(af[im][3])
                    : "r"(addr));
            }
            #pragma unroll
            for (int in2 = 0; in2 < 2; ++in2) {
                int r = wn * 32 + in2 * 16 + (lane & 7) + ((lane >> 4) << 3);
                int c = ks * 16 + ((lane >> 3) & 1) * 8;
                uint32_t addr = s2u(&bs[r * PAD + c]);
                asm volatile(
                    "ldmatrix.sync.aligned.m8n8.x4.shared.b16 {%0,%1,%2,%3}, [%4];\n"
                    : "=r"(bf[in2 * 2][0]), "=r"(bf[in2 * 2][1]),
                      "=r"(bf[in2 * 2 + 1][0]), "=r"(bf[in2 * 2 + 1][1])
                    : "r"(addr));
            }
            #pragma unroll
            for (int im = 0; im < 4; ++im)
                #pragma unroll
                for (int in = 0; in < 4; ++in) {
                    asm volatile(
                        "mma.sync.aligned.m16n8k16.row.col.f32.bf16.bf16.f32 "
                        "{%0,%1,%2,%3}, {%4,%5,%6,%7}, {%8,%9}, {%0,%1,%2,%3};\n"
                        : "+f"(acc[im][in][0]), "+f"(acc[im][in][1]),
                          "+f"(acc[im][in][2]), "+f"(acc[im][in][3])
                        : "r"(af[im][0]), "r"(af[im][1]), "r"(af[im][2]), "r"(af[im][3]),
                          "r"(bf[in][0]), "r"(bf[in][1]));
                }
        }
    }

    // epilogue: d2 = a2 + b2 - 2*dot -> packed min key per row
    const int tig = lane & 3, grp = lane >> 2;
    #pragma unroll
    for (int im = 0; im < 4; ++im) {
        int r0 = wm * 64 + im * 16 + grp;
        int r1 = r0 + 8;
        float a20 = sa2[r0], a21 = sa2[r1];
        unsigned long long k0 = ~0ULL, k1 = ~0ULL;
        #pragma unroll
        for (int in = 0; in < 4; ++in) {
            int cl = wn * 32 + in * 8 + 2 * tig;
            unsigned j0 = (unsigned)(bx * BN + cl);
            float b20 = sb2[cl], b21 = sb2[cl + 1];

            float d;
            unsigned long long kk;
            d = fmaxf(a20 + b20 - 2.f * acc[im][in][0], 0.f);
            kk = ((unsigned long long)__float_as_uint(d) << 32) | j0;
            k0 = kk < k0 ? kk : k0;
            d = fmaxf(a20 + b21 - 2.f * acc[im][in][1], 0.f);
            kk = ((unsigned long long)__float_as_uint(d) << 32) | (j0 + 1);
            k0 = kk < k0 ? kk : k0;
            d = fmaxf(a21 + b20 - 2.f * acc[im][in][2], 0.f);
            kk = ((unsigned long long)__float_as_uint(d) << 32) | j0;
            k1 = kk < k1 ? kk : k1;
            d = fmaxf(a21 + b21 - 2.f * acc[im][in][3], 0.f);
            kk = ((unsigned long long)__float_as_uint(d) << 32) | (j0 + 1);
            k1 = kk < k1 ? kk : k1;
        }
        atomicMin(&skey[r0], k0);
        atomicMin(&skey[r1], k1);
    }
    __syncthreads();

    if (tid < BM) {
        int gi = by * BM + tid;
        if (gi < N_PATCH) atomicMin(&g_minkey[gi], skey[tid]);
    }
}

// ---------------- min_val + packed argmax (parallel) ---------------------------
__global__ void k_minval() {
    __shared__ unsigned long long sk[256];
    int t = threadIdx.x;
    int i = blockIdx.x * blockDim.x + t;
    unsigned long long key = 0ULL;
    if (i < N_PATCH) {
        unsigned long long k = g_minkey[i];
        float v = sqrtf(__uint_as_float((unsigned)(k >> 32)));
        g_minval[i] = v;
        key = ((unsigned long long)__float_as_uint(v) << 32)
            | (unsigned)(0xFFFFFFFFu - (unsigned)i);   // max value, then min index
    }
    sk[t] = key; __syncthreads();
    for (int s = 128; s; s >>= 1) {
        if (t < s) { if (sk[t + s] > sk[t]) sk[t] = sk[t + s]; }
        __syncthreads();
    }
    if (t == 0) atomicMax(&g_amax_key, sk[0]);
}

// ---------------- distances of m_star to whole bank --------------------------
__global__ void k_wdist(const float* __restrict__ lib) {
    int w = (blockIdx.x * blockDim.x + threadIdx.x) >> 5;
    int lane = threadIdx.x & 31;
    if (w >= N_LIB) return;
    int sidx = (int)(0xFFFFFFFFu - (unsigned)(g_amax_key & 0xFFFFFFFFu));
    int mstar = (int)(g_minkey[sidx] & 0xFFFFFFFFu);
    const float* ms = lib + (size_t)mstar * DIM;
    const float* rj = lib + (size_t)w * DIM;
    float s = 0.f;
    for (int d = lane * 4; d < DIM; d += 128) {
        float4 a = *(const float4*)(rj + d);
        float4 b = *(const float4*)(ms + d);
        float dx = a.x - b.x, dy = a.y - b.y, dz = a.z - b.z, dw = a.w - b.w;
        s += dx * dx + dy * dy + dz * dz + dw * dw;
    }
    #pragma unroll
    for (int off = 16; off; off >>= 1) s += __shfl_down_sync(0xffffffffu, s, off);
    if (lane == 0) g_wdist2[w] = s;
}

// ---------------- fused: 3 smallest + final scalar score ----------------------
__device__ __forceinline__ void ins3(unsigned long long k, unsigned long long* b) {
    if (k < b[2]) {
        if (k < b[1]) {
            b[2] = b[1];
            if (k < b[0]) { b[1] = b[0]; b[0] = k; } else b[1] = k;
        } else b[2] = k;
    }
}

__global__ void k_top3_score(const float* __restrict__ patch,
                             const float* __restrict__ mean,
                             const float* __restrict__ stdv,
                             const float* __restrict__ lib,
                             float* __restrict__ out) {
    __shared__ unsigned long long sk[1024][3];
    __shared__ float sa[1024], sb[1024];
    int t = threadIdx.x;

    // phase 1: top-3 smallest of wdist (stable by index)
    unsigned long long b3[3] = {~0ULL, ~0ULL, ~0ULL};
    for (int j = t; j < N_LIB; j += 1024) {
        unsigned long long key =
            ((unsigned long long)__float_as_uint(g_wdist2[j]) << 32) | (unsigned)j;
        ins3(key, b3);
    }
    sk[t][0] = b3[0]; sk[t][1] = b3[1]; sk[t][2] = b3[2];
    __syncthreads();
    for (int s = 512; s; s >>= 1) {
        if (t < s) {
            ins3(sk[t + s][0], &sk[t][0]);
            ins3(sk[t + s][1], &sk[t][0]);
            ins3(sk[t + s][2], &sk[t][0]);
        }
        __syncthreads();
    }
    int nn1 = (int)(sk[0][1] & 0xFFFFFFFFu);
    int nn2 = (int)(sk[0][2] & 0xFFFFFFFFu);

    // phase 2: score using nn1, nn2 (all threads have them post-sync)
    unsigned long long ak = g_amax_key;
    int sidx = (int)(0xFFFFFFFFu - (unsigned)(ak & 0xFFFFFFFFu));
    float sstar = __uint_as_float((unsigned)(ak >> 32));
    float mu = mean[0], inv = 1.f / stdv[0];
    const float* mt = patch + (size_t)sidx * DIM;
    const float* n1 = lib + (size_t)nn1 * DIM;
    const float* n2 = lib + (size_t)nn2 * DIM;
    float a = 0.f, b = 0.f;
    if (t < DIM) {
        float m = (mt[t] - mu) * inv;
        float x = m - n1[t]; a = x * x;
        float y = m - n2[t]; b = y * y;
    }
    sa[t] = a; sb[t] = b; __syncthreads();
    for (int s = 512; s; s >>= 1) {
        if (t < s) { sa[t] += sa[t + s]; sb[t] += sb[t + s]; }
        __syncthreads();
    }
    if (t == 0) {
        float sq = sqrtf((float)DIM);
        float k0 = sqrtf(fmaxf(sa[0], 0.f));
        float k1 = sqrtf(fmaxf(sb[0], 0.f));
        float w = 1.0f - expf(sstar / sq) / (expf(k0 / sq) + expf(k1 / sq));
        out[0] = w * sstar;
    }
}

// ---------------- fused resize(56->224) + horizontal blur ---------------------
__device__ __forceinline__ int refl(int i, int n) {
    if (i < 0) i = -i;
    if (i >= n) i = 2 * n - 2 - i;
    return i;
}
__device__ __forceinline__ void gweights(float* w) {
    float s = 0.f;
    #pragma unroll
    for (int t = 0; t < 9; ++t) { float d = (float)(t - 4); w[t] = expf(-d * d / 32.0f); s += w[t]; }
    #pragma unroll
    for (int t = 0; t < 9; ++t) w[t] /= s;
}
__device__ __forceinline__ float resized_val(int y, int x) {
    float fy = (y + 0.5f) * 0.25f - 0.5f;
    float fx = (x + 0.5f) * 0.25f - 0.5f;
    int y0 = (int)floorf(fy); float wy = fy - (float)y0;
    int x0 = (int)floorf(fx); float wx = fx - (float)x0;
    int y0c = min(max(y0, 0), FH - 1), y1c = min(max(y0 + 1, 0), FH - 1);
    int x0c = min(max(x0, 0), FH - 1), x1c = min(max(x0 + 1, 0), FH - 1);
    float v00 = g_minval[y0c * FH + x0c];
    float v01 = g_minval[y0c * FH + x1c];
    float v10 = g_minval[y1c * FH + x0c];
    float v11 = g_minval[y1c * FH + x1c];
    return v00 * (1.f - wy) * (1.f - wx) + v01 * (1.f - wy) * wx
         + v10 * wy * (1.f - wx) + v11 * wy * wx;
}
__global__ void k_resize_blur_h() {
    int idx = blockIdx.x * blockDim.x + threadIdx.x;
    if (idx >= IMG * IMG) return;
    int y = idx / IMG, x = idx % IMG;
    float w[9]; gweights(w);
    float acc = 0.f;
    #pragma unroll
    for (int t = 0; t < 9; ++t) acc += w[t] * resized_val(y, refl(x + t - 4, IMG));
    g_tmp[idx] = acc;
}
__global__ void k_blur_v(float* __restrict__ out) {
    int idx = blockIdx.x * blockDim.x + threadIdx.x;
    if (idx >= IMG * IMG) return;
    int y = idx / IMG, x = idx % IMG;
    float w[9]; gweights(w);
    float acc = 0.f;
    #pragma unroll
    for (int t = 0; t < 9; ++t) acc += w[t] * g_tmp[refl(y + t - 4, IMG) * IMG + x];
    out[idx] = acc;
}

// ---------------- launch ------------------------------------------------------
extern "C" void kernel_launch(void* const* d_in, const int* in_sizes, int n_in,
                              void* d_out, int out_size) {
    const float* patch = (const float*)d_in[0];
    const float* lib   = (const float*)d_in[1];
    const float* mean  = (const float*)d_in[2];
    const float* stdv  = (const float*)d_in[3];
    float* out = (float*)d_out;

    cudaFuncSetAttribute(k_gemm_min_tc,
                         cudaFuncAttributeMaxDynamicSharedMemorySize, SMEM_TOTAL);

    k_prep<<<((N_PAD + N_LIB) * 32 + 255) / 256, 256>>>(patch, lib, mean, stdv);

    dim3 grid(N_LIB / BN, N_PAD / BM);
    k_gemm_min_tc<<<grid, 256, SMEM_TOTAL>>>();

    k_minval<<<(N_PATCH + 255) / 256, 256>>>();
    k_wdist<<<(N_LIB * 32 + 255) / 256, 256>>>(lib);
    k_top3_score<<<1, 1024>>>(patch, mean, stdv, lib, out);

    k_resize_blur_h<<<(IMG * IMG + 255) / 256, 256>>>();
    k_blur_v<<<(IMG * IMG + 255) / 256, 256>>>(out + 1);
}